// round 13
// baseline (speedup 1.0000x reference)
#include <cuda_runtime.h>
#include <math.h>

#define BN 4
#define CN 64
#define HN 128
#define WN 128
#define HWN 16384
#define TCH 20   // channel-last tile stride (16 ci + 4 pad)

// ---------------- scratch ----------------
__device__ float g_offp[2 * BN * 18 * HWN];
__device__ float g_maskp[2 * BN * 9 * HWN];
__device__ float g_wc[64 * 9 * 28];
__device__ float g_part[BN * 64 * 32 * 2];    // per (b, blk, group): sum, sumsq

typedef unsigned long long u64;

__device__ __forceinline__ u64 fma2(u64 a, u64 b, u64 c) {
    u64 d; asm("fma.rn.f32x2 %0, %1, %2, %3;" : "=l"(d) : "l"(a), "l"(b), "l"(c)); return d;
}
__device__ __forceinline__ u64 mul2(u64 a, u64 b) {
    u64 d; asm("mul.rn.f32x2 %0, %1, %2;" : "=l"(d) : "l"(a), "l"(b)); return d;
}
__device__ __forceinline__ u64 pack2(float x, float y) {
    u64 d; asm("mov.b64 %0, {%1, %2};" : "=l"(d) : "f"(x), "f"(y)); return d;
}
__device__ __forceinline__ float2 unpack2(u64 v) {
    float2 r; asm("mov.b64 {%0, %1}, %2;" : "=f"(r.x), "=f"(r.y) : "l"(v)); return r;
}

// ---------------- kernel 0: compose 1x1 into 3x3 weights (parallel) ----------------
__global__ __launch_bounds__(64) void k_compose(const float* __restrict__ w_off1,
                                                const float* __restrict__ w_off2,
                                                const float* __restrict__ w_mask1,
                                                const float* __restrict__ w_mask2)
{
    int tap = blockIdx.x / 28, co = blockIdx.x % 28;
    int ci = threadIdx.x;
    __shared__ float w2row[64];

    const float* w1 = (co < 18) ? w_off1 : w_mask1;
    if (co < 18)      w2row[ci] = w_off2[(co * 64 + ci) * 9 + tap];
    else if (co < 27) w2row[ci] = w_mask2[((co - 18) * 64 + ci) * 9 + tap];
    else              w2row[ci] = 0.f;
    __syncthreads();

    float s = 0.f;
    if (co < 27) {
#pragma unroll 8
        for (int c = 0; c < 64; c++)
            s += w1[c * 64 + ci] * w2row[c];
    }
    g_wc[ci * 252 + tap * 28 + co] = s;
}

// ---------------- kernel 1: fused 3x3 conv, split-K, packed-duplicate tile ----------------
// block 256 = 32 cols x 4 row-slots x 2 co-halves; tile 8 rows x 64 cols.
// dynamic smem: tile 8*10*67 u64 (42.9KB) + sw 2016 floats (8KB) = 50.9KB
#define CONV_SMEM (8 * 10 * 67 * 8 + 2016 * 4)

__global__ __launch_bounds__(256, 2) void k_conv(const float* __restrict__ x)
{
    extern __shared__ __align__(16) unsigned char smraw[];
    u64 (*tile)[10][67] = (u64(*)[10][67])smraw;
    float* sw = (float*)(smraw + 8 * 10 * 67 * 8);   // [ci 8][tap 9][co 28]

    int tid = threadIdx.x;
    int bz = blockIdx.z;
    int b = bz >> 1, half = bz & 1;
    int tx0 = blockIdx.x * 64, ty0 = blockIdx.y * 8;
    int tx = tid & 31;
    int s = tid >> 5;          // 0..7
    int r0 = s & 3;            // row slot
    int h = s >> 2;            // co half

    u64 a00[7], a01[7], a10[7], a11[7];
#pragma unroll
    for (int j = 0; j < 7; j++) { a00[j] = 0ULL; a01[j] = 0ULL; a10[j] = 0ULL; a11[j] = 0ULL; }

    for (int ch = 0; ch < 4; ch++) {
        int ci0 = half * 32 + ch * 8;
        __syncthreads();
        for (int i = tid; i < 8 * 10 * 66; i += 256) {
            int ci = i / 660, r = i % 660, iy = r / 66, ix = r % 66;
            int gy = ty0 - 1 + iy, gx = tx0 - 1 + ix;
            float v = 0.f;
            if ((unsigned)gy < 128u && (unsigned)gx < 128u)
                v = x[((size_t)(b * 64 + ci0 + ci)) * HWN + gy * WN + gx];
            tile[ci][iy][ix] = pack2(v, v);
        }
        for (int i = tid; i < 2016; i += 256)
            sw[i] = g_wc[ci0 * 252 + i];
        __syncthreads();

#pragma unroll 1
        for (int ci = 0; ci < 8; ci++) {
#pragma unroll
            for (int ky = 0; ky < 3; ky++) {
                const u64* rA = &tile[ci][r0 + ky][tx];
                const u64* rB = &tile[ci][r0 + 4 + ky][tx];
#pragma unroll
                for (int kx = 0; kx < 3; kx++) {
                    u64 X00 = rA[kx], X01 = rA[kx + 32];
                    u64 X10 = rB[kx], X11 = rB[kx + 32];
                    const u64* wp = (const u64*)&sw[ci * 252 + (ky * 3 + kx) * 28 + h * 14];
#pragma unroll
                    for (int j = 0; j < 7; j++) {
                        u64 w = wp[j];
                        a00[j] = fma2(X00, w, a00[j]);
                        a01[j] = fma2(X01, w, a01[j]);
                        a10[j] = fma2(X10, w, a10[j]);
                        a11[j] = fma2(X11, w, a11[j]);
                    }
                }
            }
        }
    }

    float* offp  = g_offp  + (size_t)half * (BN * 18 * HWN) + (size_t)b * 18 * HWN;
    float* maskp = g_maskp + (size_t)half * (BN * 9 * HWN) + (size_t)b * 9 * HWN;
#pragma unroll
    for (int p = 0; p < 2; p++) {
#pragma unroll
        for (int qc = 0; qc < 2; qc++) {
            int hw = (ty0 + r0 + p * 4) * WN + tx0 + tx + qc * 32;
            const u64* acc = p ? (qc ? a11 : a10) : (qc ? a01 : a00);
#pragma unroll
            for (int j = 0; j < 7; j++) {
                float2 v = unpack2(acc[j]);
                int c0 = h * 14 + 2 * j;
#pragma unroll
                for (int e = 0; e < 2; e++) {
                    int co = c0 + e;
                    float val = e ? v.y : v.x;
                    if (co < 18) offp[(size_t)co * HWN + hw] = val;
                    else if (co < 27) maskp[(size_t)(co - 18) * HWN + hw] = val;
                }
            }
        }
    }
}

// ---------------- kernel 2: deformable sampling, double-buffered fill ----------------
// block 256 = 8 rows x 32 cols; halo 4 -> tile 16x41, channel-last; 2 tile buffers.
// dynamic smem floats: tileA 13120 | tileB 13120 | s_w 576 | red 128 = 26944 (107.8KB)
#define DEF_SMEM ((13120 * 2 + 576 + 128) * 4)

__global__ __launch_bounds__(256, 2) void k_deform(const float* __restrict__ x,
                                                   const float* __restrict__ wq,
                                                   const float* __restrict__ bias,
                                                   float* __restrict__ out)
{
    extern __shared__ __align__(16) float dsm[];
    float* tbuf[2] = { dsm, dsm + 13120 };
    float* s_w = dsm + 26240;           // [k 9][ci 64]
    float* red = dsm + 26240 + 576;     // [8][16]

    int tid = threadIdx.x;
    int b = blockIdx.z;
    int tx0 = blockIdx.x * 32, ty0 = blockIdx.y * 8;
    int blk = blockIdx.y * 4 + blockIdx.x;
    int hy0 = ty0 - 4, hx0 = tx0 - 4;
    int tx = tid & 31, ty = tid >> 5;
    int gh = ty0 + ty, gw = tx0 + tx;
    int hw = gh * WN + gw;
    int lane = tid & 31, wid = tid >> 5;

    for (int i = tid; i < 576; i += 256) s_w[i] = wq[(i & 63) * 9 + (i >> 6)];

    float a00[9], a01[9], a10[9], a11[9];
    int lyA[9], lxA[9];
    const float* o0 = g_offp + (size_t)b * 18 * HWN + hw;
    const float* o1 = o0 + (size_t)BN * 18 * HWN;
    const float* m0 = g_maskp + (size_t)b * 9 * HWN + hw;
    const float* m1 = m0 + (size_t)BN * 9 * HWN;
#pragma unroll
    for (int k = 0; k < 9; k++) {
        int ky = k / 3 - 1, kx = k % 3 - 1;
        float oy = o0[(size_t)(2 * k) * HWN] + o1[(size_t)(2 * k) * HWN];
        float ox = o0[(size_t)(2 * k + 1) * HWN] + o1[(size_t)(2 * k + 1) * HWN];
        float mraw = m0[(size_t)k * HWN] + m1[(size_t)k * HWN];
        float m = 1.f / (1.f + __expf(-mraw));
        float py = (float)(gh + ky) + oy;
        float px = (float)(gw + kx) + ox;
        float yf = floorf(py), xf = floorf(px);
        float wy = py - yf, wx = px - xf;
        float b1 = m * wy, b0v = m - b1;
        a00[k] = b0v - b0v * wx; a01[k] = b0v * wx;
        a10[k] = b1 - b1 * wx;  a11[k] = b1 * wx;
        lyA[k] = (int)yf - hy0;
        lxA[k] = (int)xf - hx0;
    }

    // fill chunk 0 into buffer 0
    {
        float* buf = tbuf[0];
        for (int i = tid; i < 16 * 41 * 16; i += 256) {
            int ci = i / 656, r = i % 656, iy = r / 41, ix = r % 41;
            int gy = hy0 + iy, gx = hx0 + ix;
            float v = 0.f;
            if ((unsigned)gy < 128u && (unsigned)gx < 128u)
                v = x[((size_t)(b * 64 + ci)) * HWN + gy * WN + gx];
            buf[(iy * 41 + ix) * TCH + ci] = v;
        }
    }

    for (int ch = 0; ch < 4; ch++) {
        int ci0 = ch * 16;
        float* tile = tbuf[ch & 1];
        __syncthreads();                     // fill(ch) visible; buf[(ch+1)&1] free
        if (ch < 3) {
            float* nbuf = tbuf[(ch + 1) & 1];
            int nci0 = (ch + 1) * 16;
            for (int i = tid; i < 16 * 41 * 16; i += 256) {
                int ci = i / 656, r = i % 656, iy = r / 41, ix = r % 41;
                int gy = hy0 + iy, gx = hx0 + ix;
                float v = 0.f;
                if ((unsigned)gy < 128u && (unsigned)gx < 128u)
                    v = x[((size_t)(b * 64 + nci0 + ci)) * HWN + gy * WN + gx];
                nbuf[(iy * 41 + ix) * TCH + ci] = v;
            }
        }

        u64 acc2[8];
#pragma unroll
        for (int j = 0; j < 8; j++) acc2[j] = 0ULL;

#pragma unroll
        for (int k = 0; k < 9; k++) {
            int ly = lyA[k], lx = lxA[k];
            if ((unsigned)ly < 15u && (unsigned)lx < 40u) {
                const float4* t4 = (const float4*)&tile[(ly * 41 + lx) * TCH];
                u64 C00 = pack2(a00[k], a00[k]);
                u64 C01 = pack2(a01[k], a01[k]);
                u64 C10 = pack2(a10[k], a10[k]);
                u64 C11 = pack2(a11[k], a11[k]);
                const u64* wk = (const u64*)&s_w[k * 64 + ci0];
#pragma unroll
                for (int cg = 0; cg < 4; cg++) {
                    float4 q00 = t4[cg];
                    float4 q01 = t4[5 + cg];
                    float4 q10 = t4[205 + cg];
                    float4 q11 = t4[210 + cg];
                    u64 tl = mul2(C00, pack2(q00.x, q00.y));
                    tl = fma2(C01, pack2(q01.x, q01.y), tl);
                    tl = fma2(C10, pack2(q10.x, q10.y), tl);
                    tl = fma2(C11, pack2(q11.x, q11.y), tl);
                    acc2[cg * 2] = fma2(wk[cg * 2], tl, acc2[cg * 2]);
                    u64 th = mul2(C00, pack2(q00.z, q00.w));
                    th = fma2(C01, pack2(q01.z, q01.w), th);
                    th = fma2(C10, pack2(q10.z, q10.w), th);
                    th = fma2(C11, pack2(q11.z, q11.w), th);
                    acc2[cg * 2 + 1] = fma2(wk[cg * 2 + 1], th, acc2[cg * 2 + 1]);
                }
            } else {
                int y0 = ly + hy0, x0v = lx + hx0;
                int y1 = y0 + 1, x1 = x0v + 1;
                bool v00 = (unsigned)y0 < 128u && (unsigned)x0v < 128u;
                bool v01 = (unsigned)y0 < 128u && (unsigned)x1 < 128u;
                bool v10 = (unsigned)y1 < 128u && (unsigned)x0v < 128u;
                bool v11 = (unsigned)y1 < 128u && (unsigned)x1 < 128u;
                float c00 = a00[k], c01 = a01[k], c10 = a10[k], c11 = a11[k];
                const float* xb = x + ((size_t)(b * 64 + ci0)) * HWN;
#pragma unroll
                for (int j = 0; j < 8; j++) {
                    const float* plo = xb + (size_t)(2 * j) * HWN;
                    const float* phi = plo + HWN;
                    float slo = c00 * (v00 ? __ldg(plo + y0 * WN + x0v) : 0.f)
                              + c01 * (v01 ? __ldg(plo + y0 * WN + x1) : 0.f)
                              + c10 * (v10 ? __ldg(plo + y1 * WN + x0v) : 0.f)
                              + c11 * (v11 ? __ldg(plo + y1 * WN + x1) : 0.f);
                    float shi = c00 * (v00 ? __ldg(phi + y0 * WN + x0v) : 0.f)
                              + c01 * (v01 ? __ldg(phi + y0 * WN + x1) : 0.f)
                              + c10 * (v10 ? __ldg(phi + y1 * WN + x0v) : 0.f)
                              + c11 * (v11 ? __ldg(phi + y1 * WN + x1) : 0.f);
                    float wlo = s_w[k * 64 + ci0 + 2 * j];
                    float whi = s_w[k * 64 + ci0 + 2 * j + 1];
                    acc2[j] = fma2(pack2(wlo, whi), pack2(slo, shi), acc2[j]);
                }
            }
        }

        float sv[8], qv[8];
#pragma unroll
        for (int j = 0; j < 8; j++) {
            float2 v = unpack2(acc2[j]);
            int c = ci0 + 2 * j;
            float vx = v.x + __ldg(bias + c);
            float vy = v.y + __ldg(bias + c + 1);
            out[((size_t)(b * 64 + c)) * HWN + hw]     = vx;
            out[((size_t)(b * 64 + c + 1)) * HWN + hw] = vy;
            sv[j] = vx + vy;
            qv[j] = vx * vx + vy * vy;
        }
#pragma unroll
        for (int off = 16; off > 0; off >>= 1) {
#pragma unroll
            for (int j = 0; j < 8; j++) {
                sv[j] += __shfl_down_sync(0xffffffffu, sv[j], off);
                qv[j] += __shfl_down_sync(0xffffffffu, qv[j], off);
            }
        }
        if (lane == 0) {
#pragma unroll
            for (int j = 0; j < 8; j++) { red[wid * 16 + j] = sv[j]; red[wid * 16 + 8 + j] = qv[j]; }
        }
        __syncthreads();
        if (tid < 16) {
            float tot = 0.f;
#pragma unroll
            for (int w = 0; w < 8; w++) tot += red[w * 16 + tid];
            int g = (ci0 >> 1) + (tid & 7);
            g_part[((b * 64 + blk) * 32 + g) * 2 + (tid >> 3)] = tot;
        }
    }
}

// ---------------- kernel 3: finalize stats + normalize + affine + GELU ----------------
__global__ __launch_bounds__(256) void k_gn_gelu(float* __restrict__ o,
                                                 const float* __restrict__ gamma,
                                                 const float* __restrict__ beta)
{
    __shared__ float s_sc, s_sh;
    size_t i0 = (size_t)blockIdx.x * 2048;     // 2048 contiguous px, single (b,c)
    int c = (int)((i0 >> 14) & 63);
    int b = (int)(i0 >> 20);
    int g = c >> 1;
    int t = threadIdx.x;
    if (t < 32) {
        float s = g_part[((b * 64 + t) * 32 + g) * 2 + 0]
                + g_part[((b * 64 + t + 32) * 32 + g) * 2 + 0];
        float q = g_part[((b * 64 + t) * 32 + g) * 2 + 1]
                + g_part[((b * 64 + t + 32) * 32 + g) * 2 + 1];
#pragma unroll
        for (int off = 16; off > 0; off >>= 1) {
            s += __shfl_down_sync(0xffffffffu, s, off);
            q += __shfl_down_sync(0xffffffffu, q, off);
        }
        if (t == 0) {
            float mean = s * (1.f / 32768.f);
            float var  = q * (1.f / 32768.f) - mean * mean;
            float rstd = rsqrtf(var + 1e-5f);
            float sc = rstd * gamma[c];
            s_sc = sc;
            s_sh = beta[c] - mean * sc;
        }
    }
    __syncthreads();
    float sc = s_sc, sh = s_sh;
    float4* p = (float4*)o + i0 / 4;
#pragma unroll
    for (int rep = 0; rep < 2; rep++) {
        float4 v = p[t + rep * 256];
        float tt;
        tt = v.x * sc + sh; v.x = 0.5f * tt * (1.f + erff(tt * 0.70710678118654752f));
        tt = v.y * sc + sh; v.y = 0.5f * tt * (1.f + erff(tt * 0.70710678118654752f));
        tt = v.z * sc + sh; v.z = 0.5f * tt * (1.f + erff(tt * 0.70710678118654752f));
        tt = v.w * sc + sh; v.w = 0.5f * tt * (1.f + erff(tt * 0.70710678118654752f));
        p[t + rep * 256] = v;
    }
}

// ---------------- launch ----------------
extern "C" void kernel_launch(void* const* d_in, const int* in_sizes, int n_in,
                              void* d_out, int out_size)
{
    const float* x       = (const float*)d_in[0];
    const float* w_off1  = (const float*)d_in[1];
    const float* w_off2  = (const float*)d_in[2];
    const float* w_mask1 = (const float*)d_in[3];
    const float* w_mask2 = (const float*)d_in[4];
    const float* weight  = (const float*)d_in[5];
    const float* bias    = (const float*)d_in[6];
    const float* gamma   = (const float*)d_in[7];
    const float* beta    = (const float*)d_in[8];
    float* out = (float*)d_out;

    cudaFuncSetAttribute(k_conv, cudaFuncAttributeMaxDynamicSharedMemorySize, CONV_SMEM);
    cudaFuncSetAttribute(k_deform, cudaFuncAttributeMaxDynamicSharedMemorySize, DEF_SMEM);

    k_compose<<<252, 64>>>(w_off1, w_off2, w_mask1, w_mask2);
    k_conv<<<dim3(2, 16, BN * 2), 256, CONV_SMEM>>>(x);
    k_deform<<<dim3(4, 16, BN), 256, DEF_SMEM>>>(x, weight, bias, out);
    k_gn_gelu<<<2048, 256>>>(out, gamma, beta);
}

// round 14
// speedup vs baseline: 1.1333x; 1.1333x over previous
#include <cuda_runtime.h>
#include <math.h>

#define BN 4
#define CN 64
#define HN 128
#define WN 128
#define HWN 16384
#define TCH 20   // channel-last tile stride (16 ci + 4 pad)

// ---------------- scratch ----------------
__device__ float g_offp[2 * BN * 18 * HWN];
__device__ float g_maskp[2 * BN * 9 * HWN];
__device__ float g_wc[64 * 9 * 28];
__device__ float g_part[BN * 64 * 32 * 2];    // per (b, blk, group): sum, sumsq

typedef unsigned long long u64;

__device__ __forceinline__ u64 fma2(u64 a, u64 b, u64 c) {
    u64 d; asm("fma.rn.f32x2 %0, %1, %2, %3;" : "=l"(d) : "l"(a), "l"(b), "l"(c)); return d;
}
__device__ __forceinline__ u64 mul2(u64 a, u64 b) {
    u64 d; asm("mul.rn.f32x2 %0, %1, %2;" : "=l"(d) : "l"(a), "l"(b)); return d;
}
__device__ __forceinline__ u64 pack2(float x, float y) {
    u64 d; asm("mov.b64 %0, {%1, %2};" : "=l"(d) : "f"(x), "f"(y)); return d;
}
__device__ __forceinline__ float2 unpack2(u64 v) {
    float2 r; asm("mov.b64 {%0, %1}, %2;" : "=f"(r.x), "=f"(r.y) : "l"(v)); return r;
}

// ---------------- kernel 0: compose 1x1 into 3x3 weights (parallel) ----------------
__global__ __launch_bounds__(64) void k_compose(const float* __restrict__ w_off1,
                                                const float* __restrict__ w_off2,
                                                const float* __restrict__ w_mask1,
                                                const float* __restrict__ w_mask2)
{
    int tap = blockIdx.x / 28, co = blockIdx.x % 28;
    int ci = threadIdx.x;
    __shared__ float w2row[64];

    const float* w1 = (co < 18) ? w_off1 : w_mask1;
    if (co < 18)      w2row[ci] = w_off2[(co * 64 + ci) * 9 + tap];
    else if (co < 27) w2row[ci] = w_mask2[((co - 18) * 64 + ci) * 9 + tap];
    else              w2row[ci] = 0.f;
    __syncthreads();

    float s = 0.f;
    if (co < 27) {
#pragma unroll 8
        for (int c = 0; c < 64; c++)
            s += w1[c * 64 + ci] * w2row[c];
    }
    g_wc[ci * 252 + tap * 28 + co] = s;
}

// ---------------- kernel 1: fused 3x3 conv, split-K, 4 px/thread, co-split ----------------
// block 256 = 32 cols x 4 row-slots x 2 co-halves; tile 8 rows x 64 cols.  (R11 exact)
__global__ __launch_bounds__(256, 2) void k_conv(const float* __restrict__ x)
{
    __shared__ __align__(16) float tile[8][10][67];
    __shared__ __align__(16) float sw[2016];         // [ci 8][tap 9][co 28]
    int tid = threadIdx.x;
    int bz = blockIdx.z;
    int b = bz >> 1, half = bz & 1;
    int tx0 = blockIdx.x * 64, ty0 = blockIdx.y * 8;
    int tx = tid & 31;
    int s = tid >> 5;          // 0..7
    int r0 = s & 3;            // row slot
    int h = s >> 2;            // co half

    u64 a00[7], a01[7], a10[7], a11[7];
#pragma unroll
    for (int j = 0; j < 7; j++) { a00[j] = 0ULL; a01[j] = 0ULL; a10[j] = 0ULL; a11[j] = 0ULL; }

    for (int ch = 0; ch < 4; ch++) {
        int ci0 = half * 32 + ch * 8;
        __syncthreads();
        for (int i = tid; i < 8 * 10 * 66; i += 256) {
            int ci = i / 660, r = i % 660, iy = r / 66, ix = r % 66;
            int gy = ty0 - 1 + iy, gx = tx0 - 1 + ix;
            float v = 0.f;
            if ((unsigned)gy < 128u && (unsigned)gx < 128u)
                v = x[((size_t)(b * 64 + ci0 + ci)) * HWN + gy * WN + gx];
            tile[ci][iy][ix] = v;
        }
        for (int i = tid; i < 2016; i += 256)
            sw[i] = g_wc[ci0 * 252 + i];
        __syncthreads();

#pragma unroll 1
        for (int ci = 0; ci < 8; ci++) {
#pragma unroll
            for (int ky = 0; ky < 3; ky++) {
                const float* rA = &tile[ci][r0 + ky][tx];
                const float* rB = &tile[ci][r0 + 4 + ky][tx];
#pragma unroll
                for (int kx = 0; kx < 3; kx++) {
                    float f00 = rA[kx],     f01 = rA[kx + 32];
                    float f10 = rB[kx],     f11 = rB[kx + 32];
                    u64 X00 = pack2(f00, f00), X01 = pack2(f01, f01);
                    u64 X10 = pack2(f10, f10), X11 = pack2(f11, f11);
                    const u64* wp = (const u64*)&sw[ci * 252 + (ky * 3 + kx) * 28 + h * 14];
#pragma unroll
                    for (int j = 0; j < 7; j++) {
                        u64 w = wp[j];
                        a00[j] = fma2(X00, w, a00[j]);
                        a01[j] = fma2(X01, w, a01[j]);
                        a10[j] = fma2(X10, w, a10[j]);
                        a11[j] = fma2(X11, w, a11[j]);
                    }
                }
            }
        }
    }

    float* offp  = g_offp  + (size_t)half * (BN * 18 * HWN) + (size_t)b * 18 * HWN;
    float* maskp = g_maskp + (size_t)half * (BN * 9 * HWN) + (size_t)b * 9 * HWN;
#pragma unroll
    for (int p = 0; p < 2; p++) {
#pragma unroll
        for (int qc = 0; qc < 2; qc++) {
            int hw = (ty0 + r0 + p * 4) * WN + tx0 + tx + qc * 32;
            const u64* acc = p ? (qc ? a11 : a10) : (qc ? a01 : a00);
#pragma unroll
            for (int j = 0; j < 7; j++) {
                float2 v = unpack2(acc[j]);
                int c0 = h * 14 + 2 * j;
#pragma unroll
                for (int e = 0; e < 2; e++) {
                    int co = c0 + e;
                    float val = e ? v.y : v.x;
                    if (co < 18) offp[(size_t)co * HWN + hw] = val;
                    else if (co < 27) maskp[(size_t)(co - 18) * HWN + hw] = val;
                }
            }
        }
    }
}

// ---------------- kernel 2: deformable sampling + GN partial stats ----------------
// block 256 = 8 rows x 32 cols; halo 2 -> tile 12x37, channel-last.
__global__ __launch_bounds__(256, 2) void k_deform(const float* __restrict__ x,
                                                   const float* __restrict__ wq,
                                                   const float* __restrict__ bias,
                                                   float* __restrict__ out)
{
    __shared__ __align__(16) float tile[12 * 37 * TCH];   // 35.5KB
    __shared__ float s_w[9 * 64];
    __shared__ float red[8][16];
    int tid = threadIdx.x;
    int b = blockIdx.z;
    int tx0 = blockIdx.x * 32, ty0 = blockIdx.y * 8;
    int blk = blockIdx.y * 4 + blockIdx.x;
    int hy0 = ty0 - 2, hx0 = tx0 - 2;
    int tx = tid & 31, ty = tid >> 5;
    int gh = ty0 + ty, gw = tx0 + tx;
    int hw = gh * WN + gw;
    int lane = tid & 31, wid = tid >> 5;

    for (int i = tid; i < 576; i += 256) s_w[i] = wq[(i & 63) * 9 + (i >> 6)];

    float a00[9], a01[9], a10[9], a11[9];
    int lyA[9], lxA[9];
    const float* o0 = g_offp + (size_t)b * 18 * HWN + hw;
    const float* o1 = o0 + (size_t)BN * 18 * HWN;
    const float* m0 = g_maskp + (size_t)b * 9 * HWN + hw;
    const float* m1 = m0 + (size_t)BN * 9 * HWN;
#pragma unroll
    for (int k = 0; k < 9; k++) {
        int ky = k / 3 - 1, kx = k % 3 - 1;
        float oy = o0[(size_t)(2 * k) * HWN] + o1[(size_t)(2 * k) * HWN];
        float ox = o0[(size_t)(2 * k + 1) * HWN] + o1[(size_t)(2 * k + 1) * HWN];
        float mraw = m0[(size_t)k * HWN] + m1[(size_t)k * HWN];
        float m = 1.f / (1.f + __expf(-mraw));
        float py = (float)(gh + ky) + oy;
        float px = (float)(gw + kx) + ox;
        float yf = floorf(py), xf = floorf(px);
        float wy = py - yf, wx = px - xf;
        float b1 = m * wy, b0v = m - b1;
        a00[k] = b0v - b0v * wx; a01[k] = b0v * wx;
        a10[k] = b1 - b1 * wx;  a11[k] = b1 * wx;
        lyA[k] = (int)yf - hy0;
        lxA[k] = (int)xf - hx0;
    }

    for (int ch = 0; ch < 4; ch++) {
        int ci0 = ch * 16;
        __syncthreads();
        for (int i = tid; i < 12 * 37 * 16; i += 256) {
            int ci = i / 444, r = i % 444, iy = r / 37, ix = r % 37;
            int gy = hy0 + iy, gx = hx0 + ix;
            float v = 0.f;
            if ((unsigned)gy < 128u && (unsigned)gx < 128u)
                v = x[((size_t)(b * 64 + ci0 + ci)) * HWN + gy * WN + gx];
            tile[(iy * 37 + ix) * TCH + ci] = v;
        }
        __syncthreads();

        u64 acc2[8];
#pragma unroll
        for (int j = 0; j < 8; j++) acc2[j] = 0ULL;

#pragma unroll
        for (int k = 0; k < 9; k++) {
            int ly = lyA[k], lx = lxA[k];
            if ((unsigned)ly < 11u && (unsigned)lx < 36u) {
                const float4* t4 = (const float4*)&tile[(ly * 37 + lx) * TCH];
                u64 C00 = pack2(a00[k], a00[k]);
                u64 C01 = pack2(a01[k], a01[k]);
                u64 C10 = pack2(a10[k], a10[k]);
                u64 C11 = pack2(a11[k], a11[k]);
                const u64* wk = (const u64*)&s_w[k * 64 + ci0];
#pragma unroll
                for (int cg = 0; cg < 4; cg++) {
                    float4 q00 = t4[cg];
                    float4 q01 = t4[5 + cg];          // lx+1  (+TCH floats)
                    float4 q10 = t4[185 + cg];        // ly+1  (+37*TCH floats)
                    float4 q11 = t4[190 + cg];
                    u64 tl = mul2(C00, pack2(q00.x, q00.y));
                    tl = fma2(C01, pack2(q01.x, q01.y), tl);
                    tl = fma2(C10, pack2(q10.x, q10.y), tl);
                    tl = fma2(C11, pack2(q11.x, q11.y), tl);
                    acc2[cg * 2] = fma2(wk[cg * 2], tl, acc2[cg * 2]);
                    u64 th = mul2(C00, pack2(q00.z, q00.w));
                    th = fma2(C01, pack2(q01.z, q01.w), th);
                    th = fma2(C10, pack2(q10.z, q10.w), th);
                    th = fma2(C11, pack2(q11.z, q11.w), th);
                    acc2[cg * 2 + 1] = fma2(wk[cg * 2 + 1], th, acc2[cg * 2 + 1]);
                }
            } else {
                int y0 = ly + hy0, x0v = lx + hx0;
                int y1 = y0 + 1, x1 = x0v + 1;
                bool v00 = (unsigned)y0 < 128u && (unsigned)x0v < 128u;
                bool v01 = (unsigned)y0 < 128u && (unsigned)x1 < 128u;
                bool v10 = (unsigned)y1 < 128u && (unsigned)x0v < 128u;
                bool v11 = (unsigned)y1 < 128u && (unsigned)x1 < 128u;
                float c00 = a00[k], c01 = a01[k], c10 = a10[k], c11 = a11[k];
                const float* xb = x + ((size_t)(b * 64 + ci0)) * HWN;
#pragma unroll
                for (int j = 0; j < 8; j++) {
                    const float* plo = xb + (size_t)(2 * j) * HWN;
                    const float* phi = plo + HWN;
                    float slo = c00 * (v00 ? __ldg(plo + y0 * WN + x0v) : 0.f)
                              + c01 * (v01 ? __ldg(plo + y0 * WN + x1) : 0.f)
                              + c10 * (v10 ? __ldg(plo + y1 * WN + x0v) : 0.f)
                              + c11 * (v11 ? __ldg(plo + y1 * WN + x1) : 0.f);
                    float shi = c00 * (v00 ? __ldg(phi + y0 * WN + x0v) : 0.f)
                              + c01 * (v01 ? __ldg(phi + y0 * WN + x1) : 0.f)
                              + c10 * (v10 ? __ldg(phi + y1 * WN + x0v) : 0.f)
                              + c11 * (v11 ? __ldg(phi + y1 * WN + x1) : 0.f);
                    float wlo = s_w[k * 64 + ci0 + 2 * j];
                    float whi = s_w[k * 64 + ci0 + 2 * j + 1];
                    acc2[j] = fma2(pack2(wlo, whi), pack2(slo, shi), acc2[j]);
                }
            }
        }

        float sv[8], qv[8];
#pragma unroll
        for (int j = 0; j < 8; j++) {
            float2 v = unpack2(acc2[j]);
            int c = ci0 + 2 * j;
            float vx = v.x + __ldg(bias + c);
            float vy = v.y + __ldg(bias + c + 1);
            out[((size_t)(b * 64 + c)) * HWN + hw]     = vx;
            out[((size_t)(b * 64 + c + 1)) * HWN + hw] = vy;
            sv[j] = vx + vy;
            qv[j] = vx * vx + vy * vy;
        }
#pragma unroll
        for (int off = 16; off > 0; off >>= 1) {
#pragma unroll
            for (int j = 0; j < 8; j++) {
                sv[j] += __shfl_down_sync(0xffffffffu, sv[j], off);
                qv[j] += __shfl_down_sync(0xffffffffu, qv[j], off);
            }
        }
        if (lane == 0) {
#pragma unroll
            for (int j = 0; j < 8; j++) { red[wid][j] = sv[j]; red[wid][8 + j] = qv[j]; }
        }
        __syncthreads();
        if (tid < 16) {
            float tot = 0.f;
#pragma unroll
            for (int w = 0; w < 8; w++) tot += red[w][tid];
            int g = (ci0 >> 1) + (tid & 7);
            g_part[((b * 64 + blk) * 32 + g) * 2 + (tid >> 3)] = tot;
        }
    }
}

// ---------------- fast erf-based GELU (A&S 7.1.26, abs err ~1.5e-7) ----------------
__device__ __forceinline__ float gelu1(float t) {
    float xx = t * 0.70710678118654752f;
    float a = fabsf(xx);
    float u = __frcp_rn(fmaf(0.3275911f, a, 1.f));
    float p = fmaf(1.061405429f, u, -1.453152027f);
    p = fmaf(p, u, 1.421413741f);
    p = fmaf(p, u, -0.284496736f);
    p = fmaf(p, u, 0.254829592f);
    p = p * u;
    float e = __expf(-a * a);
    float erfa = fmaf(-p, e, 1.f);
    float er = copysignf(erfa, xx);
    return 0.5f * t * (1.f + er);
}

// ---------------- kernel 3: finalize stats + normalize + affine + GELU ----------------
__global__ __launch_bounds__(256) void k_gn_gelu(float* __restrict__ o,
                                                 const float* __restrict__ gamma,
                                                 const float* __restrict__ beta)
{
    __shared__ float s_sc, s_sh;
    size_t i0 = (size_t)blockIdx.x * 2048;     // 2048 contiguous px, single (b,c)
    int c = (int)((i0 >> 14) & 63);
    int b = (int)(i0 >> 20);
    int g = c >> 1;
    int t = threadIdx.x;
    if (t < 32) {
        float s = g_part[((b * 64 + t) * 32 + g) * 2 + 0]
                + g_part[((b * 64 + t + 32) * 32 + g) * 2 + 0];
        float q = g_part[((b * 64 + t) * 32 + g) * 2 + 1]
                + g_part[((b * 64 + t + 32) * 32 + g) * 2 + 1];
#pragma unroll
        for (int off = 16; off > 0; off >>= 1) {
            s += __shfl_down_sync(0xffffffffu, s, off);
            q += __shfl_down_sync(0xffffffffu, q, off);
        }
        if (t == 0) {
            float mean = s * (1.f / 32768.f);
            float var  = q * (1.f / 32768.f) - mean * mean;
            float rstd = rsqrtf(var + 1e-5f);
            float sc = rstd * gamma[c];
            s_sc = sc;
            s_sh = beta[c] - mean * sc;
        }
    }
    __syncthreads();
    float sc = s_sc, sh = s_sh;
    float4* p = (float4*)o + i0 / 4;
#pragma unroll
    for (int rep = 0; rep < 2; rep++) {
        float4 v = p[t + rep * 256];
        v.x = gelu1(v.x * sc + sh);
        v.y = gelu1(v.y * sc + sh);
        v.z = gelu1(v.z * sc + sh);
        v.w = gelu1(v.w * sc + sh);
        p[t + rep * 256] = v;
    }
}

// ---------------- launch ----------------
extern "C" void kernel_launch(void* const* d_in, const int* in_sizes, int n_in,
                              void* d_out, int out_size)
{
    const float* x       = (const float*)d_in[0];
    const float* w_off1  = (const float*)d_in[1];
    const float* w_off2  = (const float*)d_in[2];
    const float* w_mask1 = (const float*)d_in[3];
    const float* w_mask2 = (const float*)d_in[4];
    const float* weight  = (const float*)d_in[5];
    const float* bias    = (const float*)d_in[6];
    const float* gamma   = (const float*)d_in[7];
    const float* beta    = (const float*)d_in[8];
    float* out = (float*)d_out;

    k_compose<<<252, 64>>>(w_off1, w_off2, w_mask1, w_mask2);
    k_conv<<<dim3(2, 16, BN * 2), 256>>>(x);
    k_deform<<<dim3(4, 16, BN), 256>>>(x, weight, bias, out);
    k_gn_gelu<<<2048, 256>>>(out, gamma, beta);
}

// round 15
// speedup vs baseline: 1.1515x; 1.0161x over previous
#include <cuda_runtime.h>
#include <math.h>

#define BN 4
#define CN 64
#define HN 128
#define WN 128
#define HWN 16384
#define TCH 20   // channel-last tile stride (16 ci + 4 pad)

// ---------------- scratch ----------------
__device__ float g_offp[2 * BN * 18 * HWN];
__device__ float g_maskp[2 * BN * 9 * HWN];
__device__ float g_wc[64 * 9 * 28];
__device__ float g_part[BN * 64 * 32 * 2];    // per (b, blk, group): sum, sumsq

typedef unsigned long long u64;

__device__ __forceinline__ u64 fma2(u64 a, u64 b, u64 c) {
    u64 d; asm("fma.rn.f32x2 %0, %1, %2, %3;" : "=l"(d) : "l"(a), "l"(b), "l"(c)); return d;
}
__device__ __forceinline__ u64 mul2(u64 a, u64 b) {
    u64 d; asm("mul.rn.f32x2 %0, %1, %2;" : "=l"(d) : "l"(a), "l"(b)); return d;
}
__device__ __forceinline__ u64 pack2(float x, float y) {
    u64 d; asm("mov.b64 %0, {%1, %2};" : "=l"(d) : "f"(x), "f"(y)); return d;
}
__device__ __forceinline__ float2 unpack2(u64 v) {
    float2 r; asm("mov.b64 {%0, %1}, %2;" : "=f"(r.x), "=f"(r.y) : "l"(v)); return r;
}

// ---------------- kernel 0: compose 1x1 into 3x3 weights (parallel) ----------------
__global__ __launch_bounds__(64) void k_compose(const float* __restrict__ w_off1,
                                                const float* __restrict__ w_off2,
                                                const float* __restrict__ w_mask1,
                                                const float* __restrict__ w_mask2)
{
    int tap = blockIdx.x / 28, co = blockIdx.x % 28;
    int ci = threadIdx.x;
    __shared__ float w2row[64];

    const float* w1 = (co < 18) ? w_off1 : w_mask1;
    if (co < 18)      w2row[ci] = w_off2[(co * 64 + ci) * 9 + tap];
    else if (co < 27) w2row[ci] = w_mask2[((co - 18) * 64 + ci) * 9 + tap];
    else              w2row[ci] = 0.f;
    __syncthreads();

    float s = 0.f;
    if (co < 27) {
#pragma unroll 8
        for (int c = 0; c < 64; c++)
            s += w1[c * 64 + ci] * w2row[c];
    }
    g_wc[ci * 252 + tap * 28 + co] = s;
}

// ---------------- kernel 1: fused 3x3 conv, split-K, 4 px/thread, co-split ----------------
// block 256 = 32 cols x 4 row-slots x 2 co-halves; tile 8 rows x 64 cols.  (R11 exact)
__global__ __launch_bounds__(256, 2) void k_conv(const float* __restrict__ x)
{
    __shared__ __align__(16) float tile[8][10][67];
    __shared__ __align__(16) float sw[2016];         // [ci 8][tap 9][co 28]
    int tid = threadIdx.x;
    int bz = blockIdx.z;
    int b = bz >> 1, half = bz & 1;
    int tx0 = blockIdx.x * 64, ty0 = blockIdx.y * 8;
    int tx = tid & 31;
    int s = tid >> 5;          // 0..7
    int r0 = s & 3;            // row slot
    int h = s >> 2;            // co half

    u64 a00[7], a01[7], a10[7], a11[7];
#pragma unroll
    for (int j = 0; j < 7; j++) { a00[j] = 0ULL; a01[j] = 0ULL; a10[j] = 0ULL; a11[j] = 0ULL; }

    for (int ch = 0; ch < 4; ch++) {
        int ci0 = half * 32 + ch * 8;
        __syncthreads();
        for (int i = tid; i < 8 * 10 * 66; i += 256) {
            int ci = i / 660, r = i % 660, iy = r / 66, ix = r % 66;
            int gy = ty0 - 1 + iy, gx = tx0 - 1 + ix;
            float v = 0.f;
            if ((unsigned)gy < 128u && (unsigned)gx < 128u)
                v = x[((size_t)(b * 64 + ci0 + ci)) * HWN + gy * WN + gx];
            tile[ci][iy][ix] = v;
        }
        for (int i = tid; i < 2016; i += 256)
            sw[i] = g_wc[ci0 * 252 + i];
        __syncthreads();

#pragma unroll 1
        for (int ci = 0; ci < 8; ci++) {
#pragma unroll
            for (int ky = 0; ky < 3; ky++) {
                const float* rA = &tile[ci][r0 + ky][tx];
                const float* rB = &tile[ci][r0 + 4 + ky][tx];
#pragma unroll
                for (int kx = 0; kx < 3; kx++) {
                    float f00 = rA[kx],     f01 = rA[kx + 32];
                    float f10 = rB[kx],     f11 = rB[kx + 32];
                    u64 X00 = pack2(f00, f00), X01 = pack2(f01, f01);
                    u64 X10 = pack2(f10, f10), X11 = pack2(f11, f11);
                    const u64* wp = (const u64*)&sw[ci * 252 + (ky * 3 + kx) * 28 + h * 14];
#pragma unroll
                    for (int j = 0; j < 7; j++) {
                        u64 w = wp[j];
                        a00[j] = fma2(X00, w, a00[j]);
                        a01[j] = fma2(X01, w, a01[j]);
                        a10[j] = fma2(X10, w, a10[j]);
                        a11[j] = fma2(X11, w, a11[j]);
                    }
                }
            }
        }
    }

    float* offp  = g_offp  + (size_t)half * (BN * 18 * HWN) + (size_t)b * 18 * HWN;
    float* maskp = g_maskp + (size_t)half * (BN * 9 * HWN) + (size_t)b * 9 * HWN;
#pragma unroll
    for (int p = 0; p < 2; p++) {
#pragma unroll
        for (int qc = 0; qc < 2; qc++) {
            int hw = (ty0 + r0 + p * 4) * WN + tx0 + tx + qc * 32;
            const u64* acc = p ? (qc ? a11 : a10) : (qc ? a01 : a00);
#pragma unroll
            for (int j = 0; j < 7; j++) {
                float2 v = unpack2(acc[j]);
                int c0 = h * 14 + 2 * j;
#pragma unroll
                for (int e = 0; e < 2; e++) {
                    int co = c0 + e;
                    float val = e ? v.y : v.x;
                    if (co < 18) offp[(size_t)co * HWN + hw] = val;
                    else if (co < 27) maskp[(size_t)(co - 18) * HWN + hw] = val;
                }
            }
        }
    }
}

// ---------------- kernel 2: deformable sampling + GN partial stats ----------------
// block 256 = 8 rows x 32 cols; halo 2 -> tile 12x37, channel-last.
// dynamic smem floats: tile 8880 | s_w 576 | scr 16*16*17=4352  -> 13808 (55.2KB)
#define DEF_SMEM ((8880 + 576 + 4352) * 4)

__global__ __launch_bounds__(256, 2) void k_deform(const float* __restrict__ x,
                                                   const float* __restrict__ wq,
                                                   const float* __restrict__ bias,
                                                   float* __restrict__ out)
{
    extern __shared__ __align__(16) float dsm[];
    float* tile = dsm;                 // [12*37][TCH]
    float* s_w  = dsm + 8880;          // [k 9][ci 64]
    float* scr  = dsm + 8880 + 576;    // [16 streams][16 cols][17]

    int tid = threadIdx.x;
    int b = blockIdx.z;
    int tx0 = blockIdx.x * 32, ty0 = blockIdx.y * 8;
    int blk = blockIdx.y * 4 + blockIdx.x;
    int hy0 = ty0 - 2, hx0 = tx0 - 2;
    int tx = tid & 31, ty = tid >> 5;
    int gh = ty0 + ty, gw = tx0 + tx;
    int hw = gh * WN + gw;

    for (int i = tid; i < 576; i += 256) s_w[i] = wq[(i & 63) * 9 + (i >> 6)];

    float a00[9], a01[9], a10[9], a11[9];
    int lyA[9], lxA[9];
    const float* o0 = g_offp + (size_t)b * 18 * HWN + hw;
    const float* o1 = o0 + (size_t)BN * 18 * HWN;
    const float* m0 = g_maskp + (size_t)b * 9 * HWN + hw;
    const float* m1 = m0 + (size_t)BN * 9 * HWN;
#pragma unroll
    for (int k = 0; k < 9; k++) {
        int ky = k / 3 - 1, kx = k % 3 - 1;
        float oy = o0[(size_t)(2 * k) * HWN] + o1[(size_t)(2 * k) * HWN];
        float ox = o0[(size_t)(2 * k + 1) * HWN] + o1[(size_t)(2 * k + 1) * HWN];
        float mraw = m0[(size_t)k * HWN] + m1[(size_t)k * HWN];
        float m = 1.f / (1.f + __expf(-mraw));
        float py = (float)(gh + ky) + oy;
        float px = (float)(gw + kx) + ox;
        float yf = floorf(py), xf = floorf(px);
        float wy = py - yf, wx = px - xf;
        float b1 = m * wy, b0v = m - b1;
        a00[k] = b0v - b0v * wx; a01[k] = b0v * wx;
        a10[k] = b1 - b1 * wx;  a11[k] = b1 * wx;
        lyA[k] = (int)yf - hy0;
        lxA[k] = (int)xf - hx0;
    }

    for (int ch = 0; ch < 4; ch++) {
        int ci0 = ch * 16;
        __syncthreads();
        for (int i = tid; i < 12 * 37 * 16; i += 256) {
            int ci = i / 444, r = i % 444, iy = r / 37, ix = r % 37;
            int gy = hy0 + iy, gx = hx0 + ix;
            float v = 0.f;
            if ((unsigned)gy < 128u && (unsigned)gx < 128u)
                v = x[((size_t)(b * 64 + ci0 + ci)) * HWN + gy * WN + gx];
            tile[(iy * 37 + ix) * TCH + ci] = v;
        }
        __syncthreads();

        u64 acc2[8];
#pragma unroll
        for (int j = 0; j < 8; j++) acc2[j] = 0ULL;

#pragma unroll
        for (int k = 0; k < 9; k++) {
            int ly = lyA[k], lx = lxA[k];
            if ((unsigned)ly < 11u && (unsigned)lx < 36u) {
                const float4* t4 = (const float4*)&tile[(ly * 37 + lx) * TCH];
                u64 C00 = pack2(a00[k], a00[k]);
                u64 C01 = pack2(a01[k], a01[k]);
                u64 C10 = pack2(a10[k], a10[k]);
                u64 C11 = pack2(a11[k], a11[k]);
                const u64* wk = (const u64*)&s_w[k * 64 + ci0];
#pragma unroll
                for (int cg = 0; cg < 4; cg++) {
                    float4 q00 = t4[cg];
                    float4 q01 = t4[5 + cg];          // lx+1  (+TCH floats)
                    float4 q10 = t4[185 + cg];        // ly+1  (+37*TCH floats)
                    float4 q11 = t4[190 + cg];
                    u64 tl = mul2(C00, pack2(q00.x, q00.y));
                    tl = fma2(C01, pack2(q01.x, q01.y), tl);
                    tl = fma2(C10, pack2(q10.x, q10.y), tl);
                    tl = fma2(C11, pack2(q11.x, q11.y), tl);
                    acc2[cg * 2] = fma2(wk[cg * 2], tl, acc2[cg * 2]);
                    u64 th = mul2(C00, pack2(q00.z, q00.w));
                    th = fma2(C01, pack2(q01.z, q01.w), th);
                    th = fma2(C10, pack2(q10.z, q10.w), th);
                    th = fma2(C11, pack2(q11.z, q11.w), th);
                    acc2[cg * 2 + 1] = fma2(wk[cg * 2 + 1], th, acc2[cg * 2 + 1]);
                }
            } else {
                int y0 = ly + hy0, x0v = lx + hx0;
                int y1 = y0 + 1, x1 = x0v + 1;
                bool v00 = (unsigned)y0 < 128u && (unsigned)x0v < 128u;
                bool v01 = (unsigned)y0 < 128u && (unsigned)x1 < 128u;
                bool v10 = (unsigned)y1 < 128u && (unsigned)x0v < 128u;
                bool v11 = (unsigned)y1 < 128u && (unsigned)x1 < 128u;
                float c00 = a00[k], c01 = a01[k], c10 = a10[k], c11 = a11[k];
                const float* xb = x + ((size_t)(b * 64 + ci0)) * HWN;
#pragma unroll
                for (int j = 0; j < 8; j++) {
                    const float* plo = xb + (size_t)(2 * j) * HWN;
                    const float* phi = plo + HWN;
                    float slo = c00 * (v00 ? __ldg(plo + y0 * WN + x0v) : 0.f)
                              + c01 * (v01 ? __ldg(plo + y0 * WN + x1) : 0.f)
                              + c10 * (v10 ? __ldg(plo + y1 * WN + x0v) : 0.f)
                              + c11 * (v11 ? __ldg(plo + y1 * WN + x1) : 0.f);
                    float shi = c00 * (v00 ? __ldg(phi + y0 * WN + x0v) : 0.f)
                              + c01 * (v01 ? __ldg(phi + y0 * WN + x1) : 0.f)
                              + c10 * (v10 ? __ldg(phi + y1 * WN + x0v) : 0.f)
                              + c11 * (v11 ? __ldg(phi + y1 * WN + x1) : 0.f);
                    float wlo = s_w[k * 64 + ci0 + 2 * j];
                    float whi = s_w[k * 64 + ci0 + 2 * j + 1];
                    acc2[j] = fma2(pack2(wlo, whi), pack2(slo, shi), acc2[j]);
                }
            }
        }

        // write out + stage per-stream values into transpose scratch
        {
            int a = tid & 15, bq = tid >> 4;
#pragma unroll
            for (int j = 0; j < 8; j++) {
                float2 v = unpack2(acc2[j]);
                int c = ci0 + 2 * j;
                float vx = v.x + __ldg(bias + c);
                float vy = v.y + __ldg(bias + c + 1);
                out[((size_t)(b * 64 + c)) * HWN + hw]     = vx;
                out[((size_t)(b * 64 + c + 1)) * HWN + hw] = vy;
                scr[(j * 16 + a) * 17 + bq]       = vx + vy;          // stream j  = sum
                scr[((8 + j) * 16 + a) * 17 + bq] = vx * vx + vy * vy; // stream 8+j = sumsq
            }
        }
        __syncthreads();
        // transpose reduce: thread (v = tid>>4, p = tid&15) sums 16 entries of stream v
        {
            int v = tid >> 4, p = tid & 15;
            float tot = 0.f;
#pragma unroll
            for (int e = 0; e < 16; e++)
                tot += scr[(v * 16 + p) * 17 + e];
#pragma unroll
            for (int off = 8; off > 0; off >>= 1)
                tot += __shfl_down_sync(0xffffffffu, tot, off);
            if (p == 0) {
                int g = (ci0 >> 1) + (v & 7);
                g_part[((b * 64 + blk) * 32 + g) * 2 + (v >> 3)] = tot;
            }
        }
    }
}

// ---------------- fast erf-based GELU (A&S 7.1.26, abs err ~1.5e-7) ----------------
__device__ __forceinline__ float gelu1(float t) {
    float xx = t * 0.70710678118654752f;
    float a = fabsf(xx);
    float den = fmaf(0.3275911f, a, 1.f);
    float u; asm("rcp.approx.f32 %0, %1;" : "=f"(u) : "f"(den));
    float p = fmaf(1.061405429f, u, -1.453152027f);
    p = fmaf(p, u, 1.421413741f);
    p = fmaf(p, u, -0.284496736f);
    p = fmaf(p, u, 0.254829592f);
    p = p * u;
    float e = __expf(-a * a);
    float erfa = fmaf(-p, e, 1.f);
    float er = copysignf(erfa, xx);
    return 0.5f * t * (1.f + er);
}

// ---------------- kernel 3: finalize stats + normalize + affine + GELU ----------------
__global__ __launch_bounds__(256) void k_gn_gelu(float* __restrict__ o,
                                                 const float* __restrict__ gamma,
                                                 const float* __restrict__ beta)
{
    __shared__ float s_sc, s_sh;
    size_t i0 = (size_t)blockIdx.x * 2048;     // 2048 contiguous px, single (b,c)
    int c = (int)((i0 >> 14) & 63);
    int b = (int)(i0 >> 20);
    int g = c >> 1;
    int t = threadIdx.x;
    if (t < 32) {
        float s = g_part[((b * 64 + t) * 32 + g) * 2 + 0]
                + g_part[((b * 64 + t + 32) * 32 + g) * 2 + 0];
        float q = g_part[((b * 64 + t) * 32 + g) * 2 + 1]
                + g_part[((b * 64 + t + 32) * 32 + g) * 2 + 1];
#pragma unroll
        for (int off = 16; off > 0; off >>= 1) {
            s += __shfl_down_sync(0xffffffffu, s, off);
            q += __shfl_down_sync(0xffffffffu, q, off);
        }
        if (t == 0) {
            float mean = s * (1.f / 32768.f);
            float var  = q * (1.f / 32768.f) - mean * mean;
            float rstd = rsqrtf(var + 1e-5f);
            float sc = rstd * gamma[c];
            s_sc = sc;
            s_sh = beta[c] - mean * sc;
        }
    }
    __syncthreads();
    float sc = s_sc, sh = s_sh;
    float4* p = (float4*)o + i0 / 4;
#pragma unroll
    for (int rep = 0; rep < 2; rep++) {
        float4 v = p[t + rep * 256];
        v.x = gelu1(v.x * sc + sh);
        v.y = gelu1(v.y * sc + sh);
        v.z = gelu1(v.z * sc + sh);
        v.w = gelu1(v.w * sc + sh);
        p[t + rep * 256] = v;
    }
}

// ---------------- launch ----------------
extern "C" void kernel_launch(void* const* d_in, const int* in_sizes, int n_in,
                              void* d_out, int out_size)
{
    const float* x       = (const float*)d_in[0];
    const float* w_off1  = (const float*)d_in[1];
    const float* w_off2  = (const float*)d_in[2];
    const float* w_mask1 = (const float*)d_in[3];
    const float* w_mask2 = (const float*)d_in[4];
    const float* weight  = (const float*)d_in[5];
    const float* bias    = (const float*)d_in[6];
    const float* gamma   = (const float*)d_in[7];
    const float* beta    = (const float*)d_in[8];
    float* out = (float*)d_out;

    cudaFuncSetAttribute(k_deform, cudaFuncAttributeMaxDynamicSharedMemorySize, DEF_SMEM);

    k_compose<<<252, 64>>>(w_off1, w_off2, w_mask1, w_mask2);
    k_conv<<<dim3(2, 16, BN * 2), 256>>>(x);
    k_deform<<<dim3(4, 16, BN), 256, DEF_SMEM>>>(x, weight, bias, out);
    k_gn_gelu<<<2048, 256>>>(out, gamma, beta);
}